// round 3
// baseline (speedup 1.0000x reference)
#include <cuda_runtime.h>
#include <math.h>

// Problem constants
#define CDIM    64
#define NE      2048
#define HW      4096
#define NPIX    65536            // 16 * 4096
#define NELEM   4194304          // NPIX * CDIM

// Output layout: z_q [NELEM], loss, perplexity, indices [NPIX]
#define OFF_LOSS  NELEM
#define OFF_PERP  (NELEM + 1)
#define OFF_IDX   (NELEM + 2)

// Argmax tiling: tile = 128 pixels x ALL 2048 codes -> 512 blocks
#define BP      128
#define CHUNK   64               // codes per smem chunk
#define NCH     (NE / CHUNK)     // 32
#define THREADS 256
#define GRID_ARG (NPIX / BP)     // 512

#define ZDUP_FLOATS (CDIM * 2 * BP)   // 16384 (pixel-duplicated z tile, 64KB)
#define EBUF_FLOATS (CHUNK * CDIM)    // 4096  ([k][code] chunk, 16KB)
#define SMEM_BYTES ((ZDUP_FLOATS + 2 * EBUF_FLOATS) * 4)   // 96 KB

#define OUTBLOCKS 4096

__device__ int   g_idx[NPIX];
__device__ int   g_counts[NE];
__device__ float g_partials[OUTBLOCKS];

// ---------------------------------------------------------------------------
// Kernel 1: fused GEMM-argmax over a 128px x 2048code tile (full codebook).
// zdup[k][2p] = pixel-duplicated z (f32x2-ready pairs, built once per block).
// ebuf = [k][64 codes] chunk, 16B groups XOR-swizzled by k&15 -> conflict-free
// for both the transpose-fill and the mainloop reads.
// Thread: 4 pixels x 8 codes = 16 fma.f32x2 per k, 4 LDS.128 per k.
// Block 0 additionally zeroes g_counts (fresh per graph replay, no extra kernel).
// ---------------------------------------------------------------------------
__global__ void __launch_bounds__(THREADS, 2)
vq_argmax(const float* __restrict__ z, const float* __restrict__ cb,
          float* __restrict__ out, int out_size) {
    extern __shared__ float smem[];
    float* zdup = smem;                        // [64][256]
    float* ebuf = smem + ZDUP_FLOATS;          // 2 x [64][64]

    const int tid = threadIdx.x;
    const int tx  = tid & 7;                   // code group (8 codes)
    const int ty  = tid >> 3;                  // pixel group (4 pixels)

    if (blockIdx.x == 0) {                     // zero histogram for vq_out
#pragma unroll
        for (int i = 0; i < NE / THREADS; ++i)
            g_counts[i * THREADS + tid] = 0;
    }

    const int pixBase = blockIdx.x * BP;
    const int b       = pixBase >> 12;
    const int hwBase  = pixBase & 4095;
    const float* zimg = z + (size_t)b * CDIM * HW + hwBase;

    // ---- fill zdup: read z[c][p] float4, write {x,x,y,y},{z,z,w,w} ----
#pragma unroll
    for (int it = 0; it < 8; ++it) {           // 2048 float4 items
        int item = it * THREADS + tid;
        int c = item >> 5, p4 = item & 31;
        float4 v = ((const float4*)(zimg + (size_t)c * HW))[p4];
        float* d = zdup + c * 256 + p4 * 8;
        ((float4*)d)[0] = make_float4(v.x, v.x, v.y, v.y);
        ((float4*)d)[1] = make_float4(v.z, v.z, v.w, v.w);
    }

    // ---- prefetch chunk 0 ----
    float4 pre[4];
    {
        const float4* cbt = (const float4*)cb;
#pragma unroll
        for (int it = 0; it < 4; ++it)
            pre[it] = cbt[it * THREADS + tid];
    }
    __syncthreads();

    // ---- store chunk 0 (transpose + swizzle) ----
#pragma unroll
    for (int it = 0; it < 4; ++it) {
        int item = it * THREADS + tid;
        int n = item >> 4, kq = item & 15;
        int pg = (n >> 2) ^ kq;
        float* d = ebuf + kq * 256 + pg * 4 + (n & 3);
        d[0] = pre[it].x; d[64] = pre[it].y; d[128] = pre[it].z; d[192] = pre[it].w;
    }
    __syncthreads();

    float mx[4];
    int   mi[4];
#pragma unroll
    for (int m = 0; m < 4; ++m) { mx[m] = -3.402823e38f; mi[m] = 0; }

    for (int ch = 0; ch < NCH; ++ch) {
        const float* es = ebuf + (ch & 1) * EBUF_FLOATS;

        if (ch + 1 < NCH) {
            const float4* cbt =
                (const float4*)(cb + (size_t)(ch + 1) * CHUNK * CDIM);
#pragma unroll
            for (int it = 0; it < 4; ++it)
                pre[it] = cbt[it * THREADS + tid];
        }

        unsigned long long acc[4][4];
#pragma unroll
        for (int m = 0; m < 4; ++m)
#pragma unroll
            for (int j = 0; j < 4; ++j) acc[m][j] = 0ull;

        const float* zb0 = zdup + (ty << 3);

#pragma unroll 4
        for (int kq = 0; kq < 16; ++kq) {
            const float* er = es + kq * 256;
            const float* zr = zb0 + kq * 1024;
            const int oA = ((tx ^ kq) << 2);
            const int oB = oA ^ 32;
#pragma unroll
            for (int j = 0; j < 4; ++j) {
                const ulonglong2 za = *(const ulonglong2*)(zr + j * 256);
                const ulonglong2 zc = *(const ulonglong2*)(zr + j * 256 + 4);
                const ulonglong2 ea = *(const ulonglong2*)(er + j * 64 + oA);
                const ulonglong2 eb = *(const ulonglong2*)(er + j * 64 + oB);
                unsigned long long zp4[4] = { za.x, za.y, zc.x, zc.y };
#pragma unroll
                for (int m = 0; m < 4; ++m) {
                    asm("fma.rn.f32x2 %0, %1, %2, %0;" : "+l"(acc[m][0]) : "l"(ea.x), "l"(zp4[m]));
                    asm("fma.rn.f32x2 %0, %1, %2, %0;" : "+l"(acc[m][1]) : "l"(ea.y), "l"(zp4[m]));
                    asm("fma.rn.f32x2 %0, %1, %2, %0;" : "+l"(acc[m][2]) : "l"(eb.x), "l"(zp4[m]));
                    asm("fma.rn.f32x2 %0, %1, %2, %0;" : "+l"(acc[m][3]) : "l"(eb.y), "l"(zp4[m]));
                }
            }
        }

        // fold chunk winners (ascending code order within thread -> strict >
        // keeps lowest index on ties, matching jnp.argmax)
        const int cA = ch * CHUNK + (tx << 2);
#pragma unroll
        for (int m = 0; m < 4; ++m) {
#pragma unroll
            for (int j = 0; j < 4; ++j) {
                const int c0 = (j < 2) ? (cA + j * 2) : (cA + 32 + (j - 2) * 2);
                unsigned long long t = acc[m][j];
                float v0 = __uint_as_float((unsigned)t);
                float v1 = __uint_as_float((unsigned)(t >> 32));
                if (v0 > mx[m]) { mx[m] = v0; mi[m] = c0; }
                if (v1 > mx[m]) { mx[m] = v1; mi[m] = c0 + 1; }
            }
        }

        __syncthreads();
        if (ch + 1 < NCH) {
            float* ebN = ebuf + ((ch + 1) & 1) * EBUF_FLOATS;
#pragma unroll
            for (int it = 0; it < 4; ++it) {
                int item = it * THREADS + tid;
                int n = item >> 4, kq = item & 15;
                int pg = (n >> 2) ^ kq;
                float* d = ebN + kq * 256 + pg * 4 + (n & 3);
                d[0] = pre[it].x; d[64] = pre[it].y; d[128] = pre[it].z; d[192] = pre[it].w;
            }
            __syncthreads();
        }
    }

    // ---- reduce across the 8 code-group lanes ----
#pragma unroll
    for (int off = 4; off; off >>= 1) {
#pragma unroll
        for (int m = 0; m < 4; ++m) {
            float om = __shfl_xor_sync(0xFFFFFFFFu, mx[m], off);
            int   oi = __shfl_xor_sync(0xFFFFFFFFu, mi[m], off);
            if (om > mx[m] || (om == mx[m] && oi < mi[m])) { mx[m] = om; mi[m] = oi; }
        }
    }

    if (tx == 0) {
        const int p0 = pixBase + ty * 4;
#pragma unroll
        for (int m = 0; m < 4; ++m) {
            g_idx[p0 + m] = mi[m];
            int o = OFF_IDX + p0 + m;
            if (o < out_size) out[o] = (float)mi[m];
        }
    }
}

// ---------------------------------------------------------------------------
// Kernel 2: z_q gather + straight-through output + MSE partials + histogram.
// ---------------------------------------------------------------------------
__global__ void __launch_bounds__(256)
vq_out(const float* __restrict__ z, const float* __restrict__ cb,
       float* __restrict__ out) {
    const int t = blockIdx.x * 256 + threadIdx.x;   // float4 index
    const int e = t * 4;
    const int c  = (e >> 12) & 63;
    const int b  = e >> 18;
    const int hw = e & 4095;
    const int p  = (b << 12) + hw;

    const float4 zv = *(const float4*)(z + e);
    const int4  iv  = *(const int4*)(g_idx + p);

    const float q0 = cb[iv.x * CDIM + c];
    const float q1 = cb[iv.y * CDIM + c];
    const float q2 = cb[iv.z * CDIM + c];
    const float q3 = cb[iv.w * CDIM + c];

    float4 ov;
    ov.x = zv.x + (q0 - zv.x);
    ov.y = zv.y + (q1 - zv.y);
    ov.z = zv.z + (q2 - zv.z);
    ov.w = zv.w + (q3 - zv.w);
    *(float4*)(out + e) = ov;

    if (c == 0) {
        atomicAdd(&g_counts[iv.x], 1);
        atomicAdd(&g_counts[iv.y], 1);
        atomicAdd(&g_counts[iv.z], 1);
        atomicAdd(&g_counts[iv.w], 1);
    }

    const float d0 = q0 - zv.x, d1 = q1 - zv.y, d2 = q2 - zv.z, d3 = q3 - zv.w;
    float s = d0 * d0 + d1 * d1 + d2 * d2 + d3 * d3;

    __shared__ float red[256];
    red[threadIdx.x] = s;
    __syncthreads();
#pragma unroll
    for (int off = 128; off; off >>= 1) {
        if (threadIdx.x < off) red[threadIdx.x] += red[threadIdx.x + off];
        __syncthreads();
    }
    if (threadIdx.x == 0) g_partials[blockIdx.x] = red[0];
}

// ---------------------------------------------------------------------------
// Kernel 3: deterministic finalize — loss and perplexity (1024 threads).
// ---------------------------------------------------------------------------
__global__ void vq_fin(float* __restrict__ out, int out_size) {
    __shared__ float red[1024];
    const int t = threadIdx.x;

    float s = 0.0f;
#pragma unroll
    for (int i = 0; i < OUTBLOCKS / 1024; ++i) s += g_partials[i * 1024 + t];
    red[t] = s;
    __syncthreads();
#pragma unroll
    for (int off = 512; off; off >>= 1) {
        if (t < off) red[t] += red[t + off];
        __syncthreads();
    }
    if (t == 0 && OFF_LOSS < out_size)
        out[OFF_LOSS] = 1.25f * red[0] * (1.0f / (float)NELEM);
    __syncthreads();

    float h = 0.0f;
#pragma unroll
    for (int i = 0; i < NE / 1024; ++i) {
        float em = (float)g_counts[i * 1024 + t] * (1.0f / (float)NPIX);
        h += em * logf(em + 1e-10f);
    }
    red[t] = h;
    __syncthreads();
#pragma unroll
    for (int off = 512; off; off >>= 1) {
        if (t < off) red[t] += red[t + off];
        __syncthreads();
    }
    if (t == 0 && OFF_PERP < out_size)
        out[OFF_PERP] = expf(-red[0]);
}

// ---------------------------------------------------------------------------
extern "C" void kernel_launch(void* const* d_in, const int* in_sizes, int n_in,
                              void* d_out, int out_size) {
    const float* z  = (const float*)d_in[0];
    const float* cb = (const float*)d_in[1];
    float* out = (float*)d_out;

    cudaFuncSetAttribute(vq_argmax, cudaFuncAttributeMaxDynamicSharedMemorySize,
                         SMEM_BYTES);

    vq_argmax<<<GRID_ARG, THREADS, SMEM_BYTES>>>(z, cb, out, out_size);
    vq_out<<<OUTBLOCKS, 256>>>(z, cb, out);
    vq_fin<<<1, 1024>>>(out, out_size);
}